// round 13
// baseline (speedup 1.0000x reference)
#include <cuda_runtime.h>
#include <cuda_bf16.h>
#include <cuda_fp16.h>
#include <cstdint>
#include <math.h>

// Problem constants (fixed by the dataset)
#define NMAX 50000
#define EMAX 400000
#define ETMAX (NMAX + EMAX)   // edges + self loops
#define HEADS 4
#define HID 128

// ---------------- static scratch (no allocations allowed) ----------------
__device__ __align__(16) __half g_Hbuf[(size_t)NMAX * 512];       // GEMM output h (fp16, aggregate input)
__device__ __align__(16) __nv_bfloat16 g_Abuf[(size_t)NMAX * 512];// activations bf16 (GEMM A operand)
__device__ __align__(16) float g_attn[18 * NMAX];                 // As1 Ad1 As2 Ad2 As3 Ad3 (packed)
__device__ __align__(16) float g_m[NMAX * HEADS];                 // per-(node,head) softmax max
__device__ __align__(16) float g_rinv[NMAX * HEADS];              // per-(node,head) 1/sum
__device__ __align__(16) __nv_bfloat16 g_W1b[64 * 512];           // bf16 transposed weights [n][k]
__device__ __align__(16) __nv_bfloat16 g_W2b[512 * 512];
__device__ __align__(16) __nv_bfloat16 g_W3b[512 * 128];
__device__ int g_deg[NMAX];
__device__ int g_incl[NMAX];
__device__ int g_bsum[64];
__device__ int g_boff[64];
__device__ int g_rowptr[NMAX + 1];
__device__ int g_col[ETMAX];
__device__ int g_widx[NMAX];

// ---------------- helpers ----------------
__device__ __forceinline__ uint32_t smem_u32(const void* p) {
    uint32_t a;
    asm("{ .reg .u64 t; cvta.to.shared.u64 t, %1; cvt.u32.u64 %0, t; }" : "=r"(a) : "l"(p));
    return a;
}
__device__ __forceinline__ void ldsm4(uint32_t& r0, uint32_t& r1, uint32_t& r2, uint32_t& r3, uint32_t addr) {
    asm volatile("ldmatrix.sync.aligned.m8n8.x4.shared.b16 {%0,%1,%2,%3}, [%4];"
                 : "=r"(r0), "=r"(r1), "=r"(r2), "=r"(r3) : "r"(addr));
}
__device__ __forceinline__ void ldsm2(uint32_t& r0, uint32_t& r1, uint32_t addr) {
    asm volatile("ldmatrix.sync.aligned.m8n8.x2.shared.b16 {%0,%1}, [%2];"
                 : "=r"(r0), "=r"(r1) : "r"(addr));
}
__device__ __forceinline__ void mma_bf16(float* c, const uint32_t* a, uint32_t b0, uint32_t b1) {
    asm volatile("mma.sync.aligned.m16n8k16.row.col.f32.bf16.bf16.f32 "
                 "{%0,%1,%2,%3}, {%4,%5,%6,%7}, {%8,%9}, {%0,%1,%2,%3};"
                 : "+f"(c[0]), "+f"(c[1]), "+f"(c[2]), "+f"(c[3])
                 : "r"(a[0]), "r"(a[1]), "r"(a[2]), "r"(a[3]), "r"(b0), "r"(b1));
}
__device__ __forceinline__ void cp_async16(uint32_t dst, const void* src, int sbytes) {
    asm volatile("cp.async.cg.shared.global [%0], [%1], 16, %2;"
                 :: "r"(dst), "l"(src), "r"(sbytes) : "memory");
}
__device__ __forceinline__ void cp_commit() { asm volatile("cp.async.commit_group;" ::: "memory"); }
__device__ __forceinline__ void cp_wait1() { asm volatile("cp.async.wait_group 1;" ::: "memory"); }
__device__ __forceinline__ void cp_wait0() { asm volatile("cp.async.wait_group 0;" ::: "memory"); }

// ---------------- CSR construction ----------------
__global__ void k_count(const int* __restrict__ dst, int E) {
    int i = blockIdx.x * blockDim.x + threadIdx.x;
    if (i < E) atomicAdd(&g_deg[dst[i]], 1);
}
__global__ void k_scan1(int N) {
    __shared__ int sh[1024];
    int i = blockIdx.x * 1024 + threadIdx.x;
    int v = (i < N) ? (g_deg[i] + 1) : 0;   // +1 = self loop
    sh[threadIdx.x] = v;
    __syncthreads();
    for (int off = 1; off < 1024; off <<= 1) {
        int u = (threadIdx.x >= off) ? sh[threadIdx.x - off] : 0;
        __syncthreads();
        sh[threadIdx.x] += u;
        __syncthreads();
    }
    if (i < N) g_incl[i] = sh[threadIdx.x];
    if (threadIdx.x == 1023) g_bsum[blockIdx.x] = sh[1023];
}
__global__ void k_scan2(int nb) {
    __shared__ int sh[64];
    int t = threadIdx.x;
    int v = (t < nb) ? g_bsum[t] : 0;
    sh[t] = v;
    __syncthreads();
    for (int off = 1; off < 64; off <<= 1) {
        int u = (t >= off) ? sh[t - off] : 0;
        __syncthreads();
        sh[t] += u;
        __syncthreads();
    }
    g_boff[t] = sh[t] - v;
}
__global__ void k_scan3(int N) {
    int i = blockIdx.x * blockDim.x + threadIdx.x;
    if (i < N) {
        g_rowptr[i + 1] = g_incl[i] + g_boff[i >> 10];
        if (i == 0) g_rowptr[0] = 0;
    }
}
__global__ void k_fill_self(int N) {
    int i = blockIdx.x * blockDim.x + threadIdx.x;
    if (i < N) { g_col[g_rowptr[i]] = i; g_widx[i] = 1; }
}
__global__ void k_fill_edges(const int* __restrict__ src, const int* __restrict__ dst, int E) {
    int i = blockIdx.x * blockDim.x + threadIdx.x;
    if (i < E) {
        int d = dst[i];
        int p = atomicAdd(&g_widx[d], 1);
        g_col[g_rowptr[d] + p] = src[i];
    }
}

// ---------------- weight convert+transpose: out[n*K+k] = bf16(W[k*M+n]) ----------------
__global__ void k_wconv(const float* __restrict__ W, int K, int M,
                        __nv_bfloat16* __restrict__ ob) {
    int idx = blockIdx.x * blockDim.x + threadIdx.x;
    if (idx >= K * M) return;
    int n = idx / K, k = idx - n * K;
    ob[idx] = __float2bfloat16(W[(size_t)k * M + n]);
}

// ---------------- activation convert (layer-1 input x -> bf16) ----------------
__global__ void k_aconv(const float* __restrict__ X, int total) {
    int i = blockIdx.x * blockDim.x + threadIdx.x;
    if (i >= total) return;
    g_Abuf[i] = __float2bfloat16(X[i]);
}

// ---------------- HMMA bf16 GEMM with fused alpha epilogue ----------------
// C[N,M] (fp16) = A[N,K] @ W[K,M]; As/Ad += C_tile . a_src/a_dst (f32, per head).
#define PITCHB 80          // bytes per padded smem row (64 data + 16 pad)
#define BUFSZ  (128 * PITCHB)   // 10240 B per buffer
#define STAGESZ (2 * BUFSZ)     // A, B
__global__ void __launch_bounds__(256) k_gemm_mma(const __nv_bfloat16* __restrict__ Ab,
                                                  const __nv_bfloat16* __restrict__ Wb,
                                                  __half* __restrict__ C,
                                                  const float* __restrict__ avec_s,
                                                  const float* __restrict__ avec_d,
                                                  float* __restrict__ As,
                                                  float* __restrict__ Ad,
                                                  int N, int K, int M, int H) {
    extern __shared__ char smem[];
    uint32_t sb = smem_u32(smem);

    int tid = threadIdx.x;
    int lane = tid & 31, wid = tid >> 5;
    int wm = wid >> 2, wn = wid & 3;           // warp grid 2x4
    int row0 = blockIdx.y * 128, col0 = blockIdx.x * 128;
    int hd = blockIdx.x;                        // head index (tile width == HID)

    float acc[4][4][4];
#pragma unroll
    for (int i = 0; i < 4; i++)
#pragma unroll
        for (int j = 0; j < 4; j++)
#pragma unroll
            for (int q = 0; q < 4; q++) acc[i][j][q] = 0.f;

    int c0row = tid >> 1, c0col = (tid & 1) * 2;
    int arow_g = row0 + c0row;
    int brow_g = col0 + c0row;
    const __nv_bfloat16* apb = Ab + (size_t)arow_g * K + c0col * 8;
    const __nv_bfloat16* bpb = Wb + (size_t)brow_g * K + c0col * 8;
    int avalid = (arow_g < N) ? 16 : 0;
    uint32_t dbase = sb + c0row * PITCHB + c0col * 16;

    int a_row = wm * 64 + (lane & 15);
    int a_kp = (lane >> 4) * 8;
    int b_row = wn * 32 + (lane & 7);
    int b_kp = ((lane >> 3) & 1) * 8;

    int nch = K >> 5;

    {
#pragma unroll
        for (int b = 0; b < 2; b++) {
            uint32_t d = dbase + b * 16;
            cp_async16(d,         apb + b * 8, avalid);
            cp_async16(d + BUFSZ, bpb + b * 8, 16);
        }
        cp_commit();
    }

    for (int ch = 0; ch < nch; ch++) {
        if (ch + 1 < nch) {
            int koff = (ch + 1) * 32;
            uint32_t sdst = dbase + ((ch + 1) & 1) * STAGESZ;
#pragma unroll
            for (int b = 0; b < 2; b++) {
                uint32_t d = sdst + b * 16;
                cp_async16(d,         apb + koff + b * 8, avalid);
                cp_async16(d + BUFSZ, bpb + koff + b * 8, 16);
            }
            cp_commit();
            cp_wait1();
        } else {
            cp_wait0();
        }
        __syncthreads();

        uint32_t st = sb + (ch & 1) * STAGESZ;
#pragma unroll
        for (int kk = 0; kk < 32; kk += 16) {
            uint32_t av[4][4];
#pragma unroll
            for (int i = 0; i < 4; i++) {
                uint32_t off = (a_row + i * 16) * PITCHB + (kk + a_kp) * 2;
                ldsm4(av[i][0], av[i][1], av[i][2], av[i][3], st + off);
            }
#pragma unroll
            for (int j = 0; j < 4; j++) {
                uint32_t boff = (b_row + j * 8) * PITCHB + (kk + b_kp) * 2;
                uint32_t b0, b1;
                ldsm2(b0, b1, st + BUFSZ + boff);
#pragma unroll
                for (int i = 0; i < 4; i++) {
                    mma_bf16(acc[i][j], av[i], b0, b1);
                }
            }
        }
        __syncthreads();
    }

    // --- epilogue: write C (fp16) + fused alpha partial dots (f32) ---
    int crow = row0 + wm * 64 + (lane >> 2);
    int ccol_l = wn * 32 + (lane & 3) * 2;
    float as0[4], as1[4], ad0[4], ad1[4];
#pragma unroll
    for (int j = 0; j < 4; j++) {
        int c = hd * HID + ccol_l + j * 8;
        as0[j] = avec_s[c]; as1[j] = avec_s[c + 1];
        ad0[j] = avec_d[c]; ad1[j] = avec_d[c + 1];
    }
#pragma unroll
    for (int i = 0; i < 4; i++) {
        int r1 = crow + i * 16, r2 = r1 + 8;
        float s1 = 0.f, s2 = 0.f, d1 = 0.f, d2 = 0.f;
#pragma unroll
        for (int j = 0; j < 4; j++) {
            int cc = col0 + ccol_l + j * 8;
            if (r1 < N) *(__half2*)(C + (size_t)r1 * M + cc) = __floats2half2_rn(acc[i][j][0], acc[i][j][1]);
            if (r2 < N) *(__half2*)(C + (size_t)r2 * M + cc) = __floats2half2_rn(acc[i][j][2], acc[i][j][3]);
            s1 = fmaf(acc[i][j][0], as0[j], fmaf(acc[i][j][1], as1[j], s1));
            d1 = fmaf(acc[i][j][0], ad0[j], fmaf(acc[i][j][1], ad1[j], d1));
            s2 = fmaf(acc[i][j][2], as0[j], fmaf(acc[i][j][3], as1[j], s2));
            d2 = fmaf(acc[i][j][2], ad0[j], fmaf(acc[i][j][3], ad1[j], d2));
        }
#pragma unroll
        for (int off = 1; off < 4; off <<= 1) {
            s1 += __shfl_xor_sync(0xffffffffu, s1, off);
            s2 += __shfl_xor_sync(0xffffffffu, s2, off);
            d1 += __shfl_xor_sync(0xffffffffu, d1, off);
            d2 += __shfl_xor_sync(0xffffffffu, d2, off);
        }
        if ((lane & 3) == 0) {
            if (r1 < N) { atomicAdd(&As[r1 * H + hd], s1); atomicAdd(&Ad[r1 * H + hd], d1); }
            if (r2 < N) { atomicAdd(&As[r2 * H + hd], s2); atomicAdd(&Ad[r2 * H + hd], d2); }
        }
    }
}

// ---------------- per-(node,head) softmax stats: m and 1/sum ----------------
// Warp per node, H heads handled per lane-strided loop over edges with register cache.
template <int H>
__global__ void k_stats(const float* __restrict__ As, const float* __restrict__ Ad, int N) {
    int n = blockIdx.x * (blockDim.x >> 5) + (threadIdx.x >> 5);
    int lane = threadIdx.x & 31;
    if (n >= N) return;
    int beg = g_rowptr[n], end = g_rowptr[n + 1];
    float adh[H], mx[H], sm[H];
    float ecache[H][4];
#pragma unroll
    for (int h = 0; h < H; h++) {
        adh[h] = Ad[n * H + h];
        mx[h] = -1e30f;
        sm[h] = 0.f;
    }
    int cnt = 0;
    for (int j = beg + lane; j < end; j += 32) {
        int s = g_col[j];
#pragma unroll
        for (int h = 0; h < H; h++) {
            float e = As[s * H + h] + adh[h];
            e = e > 0.f ? e : 0.2f * e;           // leaky relu
            if (cnt < 4) ecache[h][cnt] = e;
            mx[h] = fmaxf(mx[h], e);
        }
        cnt++;
    }
#pragma unroll
    for (int h = 0; h < H; h++)
        for (int off = 16; off; off >>= 1)
            mx[h] = fmaxf(mx[h], __shfl_xor_sync(0xffffffffu, mx[h], off));
    int idx = 0;
    for (int j = beg + lane; j < end; j += 32) {
        if (idx < 4) {
#pragma unroll
            for (int h = 0; h < H; h++) sm[h] += __expf(ecache[h][idx] - mx[h]);
        } else {
            int s = g_col[j];
#pragma unroll
            for (int h = 0; h < H; h++) {
                float e = As[s * H + h] + adh[h];
                e = e > 0.f ? e : 0.2f * e;
                sm[h] += __expf(e - mx[h]);
            }
        }
        idx++;
    }
#pragma unroll
    for (int h = 0; h < H; h++) {
        for (int off = 16; off; off >>= 1)
            sm[h] += __shfl_xor_sync(0xffffffffu, sm[h], off);
    }
    if (lane == 0) {
#pragma unroll
        for (int h = 0; h < H; h++) {
            g_m[n * H + h] = mx[h];
            g_rinv[n * H + h] = 1.f / sm[h];
        }
    }
}

// ---------------- per-node weighted gather-aggregate (inline softmax weights) ----------------
// NT threads; thread t covers cols 4t..4t+3 (4 fp16 = one 8B load), within one head.
template <int H, int NT>
__global__ __launch_bounds__(NT) void k_aggregate(const __half* __restrict__ hbuf,
                                                  const float* __restrict__ As,
                                                  const float* __restrict__ Ad,
                                                  const float* __restrict__ bias,
                                                  int N) {
    int n = blockIdx.x;
    if (n >= N) return;
    int t = threadIdx.x;
    int hd = (H == 4) ? (t >> 5) : 0;
    float adh = Ad[n * H + hd];
    float m = g_m[n * H + hd];
    float rinv = g_rinv[n * H + hd];
    float4 acc = make_float4(0.f, 0.f, 0.f, 0.f);
    int beg = g_rowptr[n], end = g_rowptr[n + 1];
#pragma unroll 2
    for (int j = beg; j < end; j++) {
        int s = g_col[j];
        float e = As[s * H + hd] + adh;
        e = e > 0.f ? e : 0.2f * e;               // leaky relu
        float w = __expf(e - m) * rinv;
        uint2 u = ((const uint2*)(hbuf + (size_t)s * (H * HID)))[t];
        float2 f0 = __half22float2(*(__half2*)&u.x);
        float2 f1 = __half22float2(*(__half2*)&u.y);
        acc.x = fmaf(w, f0.x, acc.x);
        acc.y = fmaf(w, f0.y, acc.y);
        acc.z = fmaf(w, f1.x, acc.z);
        acc.w = fmaf(w, f1.y, acc.w);
    }
    float4 bv = ((const float4*)bias)[t];
    float o[4] = {acc.x + bv.x, acc.y + bv.y, acc.z + bv.z, acc.w + bv.w};
    ushort hi[4];
#pragma unroll
    for (int q = 0; q < 4; q++) {
        float v = o[q] > 0.f ? o[q] : (__expf(o[q]) - 1.f);   // elu
        hi[q] = __bfloat16_as_ushort(__float2bfloat16(v));
    }
    size_t o4 = (size_t)n * (H * HID) + 4 * t;
    *(uint2*)(g_Abuf + o4) = make_uint2((uint32_t)hi[0] | ((uint32_t)hi[1] << 16),
                                        (uint32_t)hi[2] | ((uint32_t)hi[3] << 16));
}

// ---------------- fc head: 32 nodes per 64-thread block (w1 L1-resident) ----------------
#define FC_NB 32
__global__ __launch_bounds__(64) void k_fc(const float* __restrict__ w1,
                                           const float* __restrict__ b1,
                                           const float* __restrict__ w2,
                                           const float* __restrict__ b2,
                                           float* __restrict__ out, int N) {
    __shared__ float xs[128];
    __shared__ float part[2];
    int t = threadIdx.x;   // 64
    float bias1 = b1[t];
    float wv2 = w2[t];
    float bias2 = b2[0];
    for (int it = 0; it < FC_NB; it++) {
        int n = blockIdx.x * FC_NB + it;
        if (n >= N) return;
        size_t base = (size_t)n * 128;
        xs[t]      = __bfloat162float(g_Abuf[base + t]);
        xs[t + 64] = __bfloat162float(g_Abuf[base + t + 64]);
        __syncthreads();
        float d0 = bias1, d1 = 0.f;
#pragma unroll 8
        for (int k = 0; k < 128; k += 2) {
            d0 = fmaf(xs[k],     w1[k * 64 + t],       d0);
            d1 = fmaf(xs[k + 1], w1[(k + 1) * 64 + t], d1);
        }
        float d = fmaxf(d0 + d1, 0.f);
        float p = d * wv2;
        for (int off = 16; off; off >>= 1) p += __shfl_xor_sync(0xffffffffu, p, off);
        if ((t & 31) == 0) part[t >> 5] = p;
        __syncthreads();
        if (t == 0) out[n] = 1.f / (1.f + __expf(-(part[0] + part[1] + bias2)));
        __syncthreads();
    }
}

// ---------------- launch ----------------
extern "C" void kernel_launch(void* const* d_in, const int* in_sizes, int n_in,
                              void* d_out, int out_size) {
    const float* x      = (const float*)d_in[0];
    const int*   eidx   = (const int*)d_in[1];
    const float* W1     = (const float*)d_in[2];
    const float* a_src1 = (const float*)d_in[3];
    const float* a_dst1 = (const float*)d_in[4];
    const float* b1     = (const float*)d_in[5];
    const float* W2     = (const float*)d_in[6];
    const float* a_src2 = (const float*)d_in[7];
    const float* a_dst2 = (const float*)d_in[8];
    const float* b2     = (const float*)d_in[9];
    const float* W3     = (const float*)d_in[10];
    const float* a_src3 = (const float*)d_in[11];
    const float* a_dst3 = (const float*)d_in[12];
    const float* b3     = (const float*)d_in[13];
    const float* fc1w   = (const float*)d_in[14];
    const float* fc1b   = (const float*)d_in[15];
    const float* fc2w   = (const float*)d_in[16];
    const float* fc2b   = (const float*)d_in[17];
    float* out = (float*)d_out;

    int N = in_sizes[0] / 64;
    int E = in_sizes[1] / 2;
    const int* srcp = eidx;
    const int* dstp = eidx + E;

    float* attn;
    __half* Hb;
    int* degp;
    __nv_bfloat16 *W1b, *W2b, *W3b, *Ab;
    cudaGetSymbolAddress((void**)&Hb, g_Hbuf);
    cudaGetSymbolAddress((void**)&attn, g_attn);
    cudaGetSymbolAddress((void**)&degp, g_deg);
    cudaGetSymbolAddress((void**)&W1b, g_W1b);
    cudaGetSymbolAddress((void**)&W2b, g_W2b);
    cudaGetSymbolAddress((void**)&W3b, g_W3b);
    cudaGetSymbolAddress((void**)&Ab, g_Abuf);

    float* As1 = attn;
    float* Ad1 = attn + 4 * NMAX;
    float* As2 = attn + 8 * NMAX;
    float* Ad2 = attn + 12 * NMAX;
    float* As3 = attn + 16 * NMAX;
    float* Ad3 = attn + 17 * NMAX;

    const int GSMEM = 2 * STAGESZ;   // 40960
    static int s_init = 0;
    static cudaStream_t s1;
    static cudaEvent_t e_fork, e_join;
    if (!s_init) {
        cudaFuncSetAttribute(k_gemm_mma, cudaFuncAttributeMaxDynamicSharedMemorySize, GSMEM);
        cudaStreamCreateWithFlags(&s1, cudaStreamNonBlocking);
        cudaEventCreateWithFlags(&e_fork, cudaEventDisableTiming);
        cudaEventCreateWithFlags(&e_join, cudaEventDisableTiming);
        s_init = 1;
    }

    int nb = (N + 1023) / 1024;
    int rowT = (N + 127) / 128;

    // ---- fork: CSR branch + W2/W3 converts on s1, concurrent with main chain ----
    cudaEventRecord(e_fork, 0);
    cudaStreamWaitEvent(s1, e_fork, 0);
    cudaMemsetAsync(degp, 0, N * sizeof(int), s1);
    k_count<<<(E + 255) / 256, 256, 0, s1>>>(dstp, E);
    k_scan1<<<nb, 1024, 0, s1>>>(N);
    k_scan2<<<1, 64, 0, s1>>>(nb);
    k_scan3<<<(N + 255) / 256, 256, 0, s1>>>(N);
    k_fill_self<<<(N + 255) / 256, 256, 0, s1>>>(N);
    k_fill_edges<<<(E + 255) / 256, 256, 0, s1>>>(srcp, dstp, E);
    k_wconv<<<(512 * 512 + 255) / 256, 256, 0, s1>>>(W2, 512, 512, W2b);
    k_wconv<<<(512 * 128 + 255) / 256, 256, 0, s1>>>(W3, 512, 128, W3b);
    cudaEventRecord(e_join, s1);

    // ---- main chain: layer-1 GEMM prerequisites + GEMM ----
    cudaMemsetAsync(attn, 0, 18 * NMAX * sizeof(float));
    k_aconv<<<(N * 64 + 255) / 256, 256>>>(x, N * 64);
    k_wconv<<<(64 * 512 + 255) / 256, 256>>>(W1, 64, 512, W1b);
    k_gemm_mma<<<dim3(4, rowT), 256, GSMEM>>>(Ab, W1b, Hb, a_src1, a_dst1, As1, Ad1, N, 64, 512, 4);

    // ---- join: need CSR + W2/W3 converts from here on ----
    cudaStreamWaitEvent(0, e_join, 0);

    k_stats<4><<<(N + 7) / 8, 256>>>(As1, Ad1, N);
    k_aggregate<4, 128><<<N, 128>>>(Hb, As1, Ad1, b1, N);

    // Layer 2: K=512, M=512
    k_gemm_mma<<<dim3(4, rowT), 256, GSMEM>>>(Ab, W2b, Hb, a_src2, a_dst2, As2, Ad2, N, 512, 512, 4);
    k_stats<4><<<(N + 7) / 8, 256>>>(As2, Ad2, N);
    k_aggregate<4, 128><<<N, 128>>>(Hb, As2, Ad2, b2, N);

    // Layer 3: K=512, M=128 (heads=1)
    k_gemm_mma<<<dim3(1, rowT), 256, GSMEM>>>(Ab, W3b, Hb, a_src3, a_dst3, As3, Ad3, N, 512, 128, 1);
    k_stats<1><<<(N + 7) / 8, 256>>>(As3, Ad3, N);
    k_aggregate<1, 32><<<N, 32>>>(Hb, As3, Ad3, b3, N);

    // MLP head
    k_fc<<<(N + FC_NB - 1) / FC_NB, 64>>>(fc1w, fc1b, fc2w, fc2b, out, N);
}

// round 14
// speedup vs baseline: 1.0275x; 1.0275x over previous
#include <cuda_runtime.h>
#include <cuda_bf16.h>
#include <cuda_fp16.h>
#include <cstdint>
#include <math.h>

// Problem constants (fixed by the dataset)
#define NMAX 50000
#define EMAX 400000
#define ETMAX (NMAX + EMAX)   // edges + self loops
#define HEADS 4
#define HID 128

// ---------------- static scratch (no allocations allowed) ----------------
__device__ __align__(16) __half g_Hbuf[(size_t)NMAX * 512];       // GEMM output h (fp16, aggregate input)
__device__ __align__(16) __nv_bfloat16 g_Abuf[(size_t)NMAX * 512];// activations bf16 (GEMM A operand)
__device__ __align__(16) float g_attn[18 * NMAX];                 // As1 Ad1 As2 Ad2 As3 Ad3 (packed)
__device__ __align__(16) float g_w[(size_t)ETMAX * HEADS];        // per-edge-per-head softmax weights
__device__ __align__(16) __nv_bfloat16 g_W1b[64 * 512];           // bf16 transposed weights [n][k]
__device__ __align__(16) __nv_bfloat16 g_W2b[512 * 512];
__device__ __align__(16) __nv_bfloat16 g_W3b[512 * 128];
__device__ int g_deg[NMAX];
__device__ int g_incl[NMAX];
__device__ int g_bsum[64];
__device__ int g_boff[64];
__device__ int g_rowptr[NMAX + 1];
__device__ int g_col[ETMAX];
__device__ int g_widx[NMAX];

// ---------------- helpers ----------------
__device__ __forceinline__ uint32_t smem_u32(const void* p) {
    uint32_t a;
    asm("{ .reg .u64 t; cvta.to.shared.u64 t, %1; cvt.u32.u64 %0, t; }" : "=r"(a) : "l"(p));
    return a;
}
__device__ __forceinline__ void ldsm4(uint32_t& r0, uint32_t& r1, uint32_t& r2, uint32_t& r3, uint32_t addr) {
    asm volatile("ldmatrix.sync.aligned.m8n8.x4.shared.b16 {%0,%1,%2,%3}, [%4];"
                 : "=r"(r0), "=r"(r1), "=r"(r2), "=r"(r3) : "r"(addr));
}
__device__ __forceinline__ void ldsm2(uint32_t& r0, uint32_t& r1, uint32_t addr) {
    asm volatile("ldmatrix.sync.aligned.m8n8.x2.shared.b16 {%0,%1}, [%2];"
                 : "=r"(r0), "=r"(r1) : "r"(addr));
}
__device__ __forceinline__ void mma_bf16(float* c, const uint32_t* a, uint32_t b0, uint32_t b1) {
    asm volatile("mma.sync.aligned.m16n8k16.row.col.f32.bf16.bf16.f32 "
                 "{%0,%1,%2,%3}, {%4,%5,%6,%7}, {%8,%9}, {%0,%1,%2,%3};"
                 : "+f"(c[0]), "+f"(c[1]), "+f"(c[2]), "+f"(c[3])
                 : "r"(a[0]), "r"(a[1]), "r"(a[2]), "r"(a[3]), "r"(b0), "r"(b1));
}
__device__ __forceinline__ void cp_async16(uint32_t dst, const void* src, int sbytes) {
    asm volatile("cp.async.cg.shared.global [%0], [%1], 16, %2;"
                 :: "r"(dst), "l"(src), "r"(sbytes) : "memory");
}
__device__ __forceinline__ void cp_commit() { asm volatile("cp.async.commit_group;" ::: "memory"); }
__device__ __forceinline__ void cp_wait2() { asm volatile("cp.async.wait_group 2;" ::: "memory"); }
__device__ __forceinline__ void cp_wait1() { asm volatile("cp.async.wait_group 1;" ::: "memory"); }
__device__ __forceinline__ void cp_wait0() { asm volatile("cp.async.wait_group 0;" ::: "memory"); }

// ---------------- CSR construction ----------------
__global__ void k_count(const int* __restrict__ dst, int E) {
    int i = blockIdx.x * blockDim.x + threadIdx.x;
    if (i < E) atomicAdd(&g_deg[dst[i]], 1);
}
__global__ void k_scan1(int N) {
    __shared__ int sh[1024];
    int i = blockIdx.x * 1024 + threadIdx.x;
    int v = (i < N) ? (g_deg[i] + 1) : 0;   // +1 = self loop
    sh[threadIdx.x] = v;
    __syncthreads();
    for (int off = 1; off < 1024; off <<= 1) {
        int u = (threadIdx.x >= off) ? sh[threadIdx.x - off] : 0;
        __syncthreads();
        sh[threadIdx.x] += u;
        __syncthreads();
    }
    if (i < N) g_incl[i] = sh[threadIdx.x];
    if (threadIdx.x == 1023) g_bsum[blockIdx.x] = sh[1023];
}
__global__ void k_scan2(int nb) {
    __shared__ int sh[64];
    int t = threadIdx.x;
    int v = (t < nb) ? g_bsum[t] : 0;
    sh[t] = v;
    __syncthreads();
    for (int off = 1; off < 64; off <<= 1) {
        int u = (t >= off) ? sh[t - off] : 0;
        __syncthreads();
        sh[t] += u;
        __syncthreads();
    }
    g_boff[t] = sh[t] - v;
}
__global__ void k_scan3(int N) {
    int i = blockIdx.x * blockDim.x + threadIdx.x;
    if (i < N) {
        g_rowptr[i + 1] = g_incl[i] + g_boff[i >> 10];
        if (i == 0) g_rowptr[0] = 0;
    }
}
__global__ void k_fill_self(int N) {
    int i = blockIdx.x * blockDim.x + threadIdx.x;
    if (i < N) { g_col[g_rowptr[i]] = i; g_widx[i] = 1; }
}
__global__ void k_fill_edges(const int* __restrict__ src, const int* __restrict__ dst, int E) {
    int i = blockIdx.x * blockDim.x + threadIdx.x;
    if (i < E) {
        int d = dst[i];
        int p = atomicAdd(&g_widx[d], 1);
        g_col[g_rowptr[d] + p] = src[i];
    }
}

// ---------------- weight convert+transpose: out[n*K+k] = bf16(W[k*M+n]) ----------------
__global__ void k_wconv(const float* __restrict__ W, int K, int M,
                        __nv_bfloat16* __restrict__ ob) {
    int idx = blockIdx.x * blockDim.x + threadIdx.x;
    if (idx >= K * M) return;
    int n = idx / K, k = idx - n * K;
    ob[idx] = __float2bfloat16(W[(size_t)k * M + n]);
}

// ---------------- activation convert (layer-1 input x -> bf16) ----------------
__global__ void k_aconv(const float* __restrict__ X, int total) {
    int i = blockIdx.x * blockDim.x + threadIdx.x;
    if (i >= total) return;
    g_Abuf[i] = __float2bfloat16(X[i]);
}

// ---------------- HMMA bf16 GEMM with fused alpha epilogue (3-stage cp.async) ----------------
// C[N,M] (fp16) = A[N,K] @ W[K,M]; As/Ad += C_tile . a_src/a_dst (f32, per head).
#define PITCHB 80          // bytes per padded smem row (64 data + 16 pad)
#define BUFSZ  (128 * PITCHB)   // 10240 B per buffer
#define STAGESZ (2 * BUFSZ)     // A, B
#define NSTAGE 3
__global__ void __launch_bounds__(256) k_gemm_mma(const __nv_bfloat16* __restrict__ Ab,
                                                  const __nv_bfloat16* __restrict__ Wb,
                                                  __half* __restrict__ C,
                                                  const float* __restrict__ avec_s,
                                                  const float* __restrict__ avec_d,
                                                  float* __restrict__ As,
                                                  float* __restrict__ Ad,
                                                  int N, int K, int M, int H) {
    extern __shared__ char smem[];
    uint32_t sb = smem_u32(smem);

    int tid = threadIdx.x;
    int lane = tid & 31, wid = tid >> 5;
    int wm = wid >> 2, wn = wid & 3;           // warp grid 2x4
    int row0 = blockIdx.y * 128, col0 = blockIdx.x * 128;
    int hd = blockIdx.x;                        // head index (tile width == HID)

    float acc[4][4][4];
#pragma unroll
    for (int i = 0; i < 4; i++)
#pragma unroll
        for (int j = 0; j < 4; j++)
#pragma unroll
            for (int q = 0; q < 4; q++) acc[i][j][q] = 0.f;

    int c0row = tid >> 1, c0col = (tid & 1) * 2;
    int arow_g = row0 + c0row;
    int brow_g = col0 + c0row;
    const __nv_bfloat16* apb = Ab + (size_t)arow_g * K + c0col * 8;
    const __nv_bfloat16* bpb = Wb + (size_t)brow_g * K + c0col * 8;
    int avalid = (arow_g < N) ? 16 : 0;
    uint32_t dbase = sb + c0row * PITCHB + c0col * 16;

    int a_row = wm * 64 + (lane & 15);
    int a_kp = (lane >> 4) * 8;
    int b_row = wn * 32 + (lane & 7);
    int b_kp = ((lane >> 3) & 1) * 8;

    int nch = K >> 5;

    // prologue: issue up to NSTAGE-1 chunk loads
#pragma unroll
    for (int s = 0; s < NSTAGE - 1; s++) {
        if (s < nch) {
            int koff = s * 32;
            uint32_t d0 = dbase + s * STAGESZ;
#pragma unroll
            for (int b = 0; b < 2; b++) {
                uint32_t d = d0 + b * 16;
                cp_async16(d,         apb + koff + b * 8, avalid);
                cp_async16(d + BUFSZ, bpb + koff + b * 8, 16);
            }
        }
        cp_commit();   // commit even if empty to keep group accounting constant
    }

    for (int ch = 0; ch < nch; ch++) {
        if (ch + NSTAGE - 1 < nch) {
            int koff = (ch + NSTAGE - 1) * 32;
            uint32_t sdst = dbase + ((ch + NSTAGE - 1) % NSTAGE) * STAGESZ;
#pragma unroll
            for (int b = 0; b < 2; b++) {
                uint32_t d = sdst + b * 16;
                cp_async16(d,         apb + koff + b * 8, avalid);
                cp_async16(d + BUFSZ, bpb + koff + b * 8, 16);
            }
            cp_commit();
            cp_wait2();          // chunk ch complete; ch+1, ch+2 may be in flight
        } else if (ch + NSTAGE - 2 < nch) {
            cp_wait1();
        } else {
            cp_wait0();
        }
        __syncthreads();

        uint32_t st = sb + (ch % NSTAGE) * STAGESZ;
#pragma unroll
        for (int kk = 0; kk < 32; kk += 16) {
            uint32_t av[4][4];
#pragma unroll
            for (int i = 0; i < 4; i++) {
                uint32_t off = (a_row + i * 16) * PITCHB + (kk + a_kp) * 2;
                ldsm4(av[i][0], av[i][1], av[i][2], av[i][3], st + off);
            }
#pragma unroll
            for (int j = 0; j < 4; j++) {
                uint32_t boff = (b_row + j * 8) * PITCHB + (kk + b_kp) * 2;
                uint32_t b0, b1;
                ldsm2(b0, b1, st + BUFSZ + boff);
#pragma unroll
                for (int i = 0; i < 4; i++) {
                    mma_bf16(acc[i][j], av[i], b0, b1);
                }
            }
        }
        __syncthreads();
    }

    // --- epilogue: write C (fp16) + fused alpha partial dots (f32) ---
    int crow = row0 + wm * 64 + (lane >> 2);
    int ccol_l = wn * 32 + (lane & 3) * 2;
    float as0[4], as1[4], ad0[4], ad1[4];
#pragma unroll
    for (int j = 0; j < 4; j++) {
        int c = hd * HID + ccol_l + j * 8;
        as0[j] = avec_s[c]; as1[j] = avec_s[c + 1];
        ad0[j] = avec_d[c]; ad1[j] = avec_d[c + 1];
    }
#pragma unroll
    for (int i = 0; i < 4; i++) {
        int r1 = crow + i * 16, r2 = r1 + 8;
        float s1 = 0.f, s2 = 0.f, d1 = 0.f, d2 = 0.f;
#pragma unroll
        for (int j = 0; j < 4; j++) {
            int cc = col0 + ccol_l + j * 8;
            if (r1 < N) *(__half2*)(C + (size_t)r1 * M + cc) = __floats2half2_rn(acc[i][j][0], acc[i][j][1]);
            if (r2 < N) *(__half2*)(C + (size_t)r2 * M + cc) = __floats2half2_rn(acc[i][j][2], acc[i][j][3]);
            s1 = fmaf(acc[i][j][0], as0[j], fmaf(acc[i][j][1], as1[j], s1));
            d1 = fmaf(acc[i][j][0], ad0[j], fmaf(acc[i][j][1], ad1[j], d1));
            s2 = fmaf(acc[i][j][2], as0[j], fmaf(acc[i][j][3], as1[j], s2));
            d2 = fmaf(acc[i][j][2], ad0[j], fmaf(acc[i][j][3], ad1[j], d2));
        }
#pragma unroll
        for (int off = 1; off < 4; off <<= 1) {
            s1 += __shfl_xor_sync(0xffffffffu, s1, off);
            s2 += __shfl_xor_sync(0xffffffffu, s2, off);
            d1 += __shfl_xor_sync(0xffffffffu, d1, off);
            d2 += __shfl_xor_sync(0xffffffffu, d2, off);
        }
        if ((lane & 3) == 0) {
            if (r1 < N) { atomicAdd(&As[r1 * H + hd], s1); atomicAdd(&Ad[r1 * H + hd], d1); }
            if (r2 < N) { atomicAdd(&As[r2 * H + hd], s2); atomicAdd(&Ad[r2 * H + hd], d2); }
        }
    }
}

// ---------------- per-node segment softmax over incoming edges ----------------
template <int H>
__global__ void k_softmax(const float* __restrict__ As, const float* __restrict__ Ad, int N) {
    int n = blockIdx.x * (blockDim.x >> 5) + (threadIdx.x >> 5);
    int lane = threadIdx.x & 31;
    if (n >= N) return;
    int beg = g_rowptr[n], end = g_rowptr[n + 1];
    float adh[H], mx[H], sm[H];
#pragma unroll
    for (int h = 0; h < H; h++) {
        adh[h] = Ad[n * H + h];
        mx[h] = -1e30f;
        sm[h] = 0.f;
    }
    for (int j = beg + lane; j < end; j += 32) {
        int s = g_col[j];
#pragma unroll
        for (int h = 0; h < H; h++) {
            float e = As[s * H + h] + adh[h];
            e = e > 0.f ? e : 0.2f * e;           // leaky relu
            g_w[(size_t)j * H + h] = e;
            mx[h] = fmaxf(mx[h], e);
        }
    }
#pragma unroll
    for (int h = 0; h < H; h++)
        for (int off = 16; off; off >>= 1)
            mx[h] = fmaxf(mx[h], __shfl_xor_sync(0xffffffffu, mx[h], off));
    for (int j = beg + lane; j < end; j += 32) {
#pragma unroll
        for (int h = 0; h < H; h++) {
            float ex = __expf(g_w[(size_t)j * H + h] - mx[h]);
            g_w[(size_t)j * H + h] = ex;
            sm[h] += ex;
        }
    }
#pragma unroll
    for (int h = 0; h < H; h++) {
        for (int off = 16; off; off >>= 1)
            sm[h] += __shfl_xor_sync(0xffffffffu, sm[h], off);
        sm[h] = 1.f / sm[h];
    }
    for (int j = beg + lane; j < end; j += 32) {
#pragma unroll
        for (int h = 0; h < H; h++) g_w[(size_t)j * H + h] *= sm[h];
    }
}

// ---------------- per-node weighted gather-aggregate + bias + elu -> bf16 ----------------
// NT threads; thread t covers cols 4t..4t+3 (4 fp16 = one 8B load), within one head.
template <int H, int NT>
__global__ __launch_bounds__(NT) void k_aggregate(const __half* __restrict__ hbuf,
                                                  const float* __restrict__ bias,
                                                  int N) {
    int n = blockIdx.x;
    if (n >= N) return;
    int t = threadIdx.x;
    int hd = (H == 4) ? (t >> 5) : 0;
    float4 acc = make_float4(0.f, 0.f, 0.f, 0.f);
    int beg = g_rowptr[n], end = g_rowptr[n + 1];
#pragma unroll 2
    for (int j = beg; j < end; j++) {
        int s = g_col[j];
        float w = g_w[(size_t)j * H + hd];
        uint2 u = ((const uint2*)(hbuf + (size_t)s * (H * HID)))[t];
        float2 f0 = __half22float2(*(__half2*)&u.x);
        float2 f1 = __half22float2(*(__half2*)&u.y);
        acc.x = fmaf(w, f0.x, acc.x);
        acc.y = fmaf(w, f0.y, acc.y);
        acc.z = fmaf(w, f1.x, acc.z);
        acc.w = fmaf(w, f1.y, acc.w);
    }
    float4 bv = ((const float4*)bias)[t];
    float o[4] = {acc.x + bv.x, acc.y + bv.y, acc.z + bv.z, acc.w + bv.w};
    ushort hi[4];
#pragma unroll
    for (int q = 0; q < 4; q++) {
        float v = o[q] > 0.f ? o[q] : (__expf(o[q]) - 1.f);   // elu
        hi[q] = __bfloat16_as_ushort(__float2bfloat16(v));
    }
    size_t o4 = (size_t)n * (H * HID) + 4 * t;
    *(uint2*)(g_Abuf + o4) = make_uint2((uint32_t)hi[0] | ((uint32_t)hi[1] << 16),
                                        (uint32_t)hi[2] | ((uint32_t)hi[3] << 16));
}

// ---------------- fc head: 16 nodes per 64-thread block (w1 L1-resident) ----------------
#define FC_NB 16
__global__ __launch_bounds__(64) void k_fc(const float* __restrict__ w1,
                                           const float* __restrict__ b1,
                                           const float* __restrict__ w2,
                                           const float* __restrict__ b2,
                                           float* __restrict__ out, int N) {
    __shared__ float xs[128];
    __shared__ float part[2];
    int t = threadIdx.x;   // 64
    float bias1 = b1[t];
    float wv2 = w2[t];
    float bias2 = b2[0];
    for (int it = 0; it < FC_NB; it++) {
        int n = blockIdx.x * FC_NB + it;
        if (n >= N) return;
        size_t base = (size_t)n * 128;
        xs[t]      = __bfloat162float(g_Abuf[base + t]);
        xs[t + 64] = __bfloat162float(g_Abuf[base + t + 64]);
        __syncthreads();
        float d0 = bias1, d1 = 0.f;
#pragma unroll 8
        for (int k = 0; k < 128; k += 2) {
            d0 = fmaf(xs[k],     w1[k * 64 + t],       d0);
            d1 = fmaf(xs[k + 1], w1[(k + 1) * 64 + t], d1);
        }
        float d = fmaxf(d0 + d1, 0.f);
        float p = d * wv2;
        for (int off = 16; off; off >>= 1) p += __shfl_xor_sync(0xffffffffu, p, off);
        if ((t & 31) == 0) part[t >> 5] = p;
        __syncthreads();
        if (t == 0) out[n] = 1.f / (1.f + __expf(-(part[0] + part[1] + bias2)));
        __syncthreads();
    }
}

// ---------------- launch ----------------
extern "C" void kernel_launch(void* const* d_in, const int* in_sizes, int n_in,
                              void* d_out, int out_size) {
    const float* x      = (const float*)d_in[0];
    const int*   eidx   = (const int*)d_in[1];
    const float* W1     = (const float*)d_in[2];
    const float* a_src1 = (const float*)d_in[3];
    const float* a_dst1 = (const float*)d_in[4];
    const float* b1     = (const float*)d_in[5];
    const float* W2     = (const float*)d_in[6];
    const float* a_src2 = (const float*)d_in[7];
    const float* a_dst2 = (const float*)d_in[8];
    const float* b2     = (const float*)d_in[9];
    const float* W3     = (const float*)d_in[10];
    const float* a_src3 = (const float*)d_in[11];
    const float* a_dst3 = (const float*)d_in[12];
    const float* b3     = (const float*)d_in[13];
    const float* fc1w   = (const float*)d_in[14];
    const float* fc1b   = (const float*)d_in[15];
    const float* fc2w   = (const float*)d_in[16];
    const float* fc2b   = (const float*)d_in[17];
    float* out = (float*)d_out;

    int N = in_sizes[0] / 64;
    int E = in_sizes[1] / 2;
    const int* srcp = eidx;
    const int* dstp = eidx + E;

    float* attn;
    __half* Hb;
    int* degp;
    __nv_bfloat16 *W1b, *W2b, *W3b, *Ab;
    cudaGetSymbolAddress((void**)&Hb, g_Hbuf);
    cudaGetSymbolAddress((void**)&attn, g_attn);
    cudaGetSymbolAddress((void**)&degp, g_deg);
    cudaGetSymbolAddress((void**)&W1b, g_W1b);
    cudaGetSymbolAddress((void**)&W2b, g_W2b);
    cudaGetSymbolAddress((void**)&W3b, g_W3b);
    cudaGetSymbolAddress((void**)&Ab, g_Abuf);

    float* As1 = attn;
    float* Ad1 = attn + 4 * NMAX;
    float* As2 = attn + 8 * NMAX;
    float* Ad2 = attn + 12 * NMAX;
    float* As3 = attn + 16 * NMAX;
    float* Ad3 = attn + 17 * NMAX;

    const int GSMEM = NSTAGE * STAGESZ;   // 61440
    static int s_init = 0;
    static cudaStream_t s1;
    static cudaEvent_t e_fork, e_join;
    if (!s_init) {
        cudaFuncSetAttribute(k_gemm_mma, cudaFuncAttributeMaxDynamicSharedMemorySize, GSMEM);
        cudaStreamCreateWithFlags(&s1, cudaStreamNonBlocking);
        cudaEventCreateWithFlags(&e_fork, cudaEventDisableTiming);
        cudaEventCreateWithFlags(&e_join, cudaEventDisableTiming);
        s_init = 1;
    }

    int nb = (N + 1023) / 1024;
    int rowT = (N + 127) / 128;

    // ---- fork: CSR branch + W2/W3 converts on s1, concurrent with main chain ----
    cudaEventRecord(e_fork, 0);
    cudaStreamWaitEvent(s1, e_fork, 0);
    cudaMemsetAsync(degp, 0, N * sizeof(int), s1);
    k_count<<<(E + 255) / 256, 256, 0, s1>>>(dstp, E);
    k_scan1<<<nb, 1024, 0, s1>>>(N);
    k_scan2<<<1, 64, 0, s1>>>(nb);
    k_scan3<<<(N + 255) / 256, 256, 0, s1>>>(N);
    k_fill_self<<<(N + 255) / 256, 256, 0, s1>>>(N);
    k_fill_edges<<<(E + 255) / 256, 256, 0, s1>>>(srcp, dstp, E);
    k_wconv<<<(512 * 512 + 255) / 256, 256, 0, s1>>>(W2, 512, 512, W2b);
    k_wconv<<<(512 * 128 + 255) / 256, 256, 0, s1>>>(W3, 512, 128, W3b);
    cudaEventRecord(e_join, s1);

    // ---- main chain: layer-1 GEMM prerequisites + GEMM ----
    cudaMemsetAsync(attn, 0, 18 * NMAX * sizeof(float));
    k_aconv<<<(N * 64 + 255) / 256, 256>>>(x, N * 64);
    k_wconv<<<(64 * 512 + 255) / 256, 256>>>(W1, 64, 512, W1b);
    k_gemm_mma<<<dim3(4, rowT), 256, GSMEM>>>(Ab, W1b, Hb, a_src1, a_dst1, As1, Ad1, N, 64, 512, 4);

    // ---- join: need CSR + W2/W3 converts from here on ----
    cudaStreamWaitEvent(0, e_join, 0);

    k_softmax<4><<<(N + 7) / 8, 256>>>(As1, Ad1, N);
    k_aggregate<4, 128><<<N, 128>>>(Hb, b1, N);

    // Layer 2: K=512, M=512
    k_gemm_mma<<<dim3(4, rowT), 256, GSMEM>>>(Ab, W2b, Hb, a_src2, a_dst2, As2, Ad2, N, 512, 512, 4);
    k_softmax<4><<<(N + 7) / 8, 256>>>(As2, Ad2, N);
    k_aggregate<4, 128><<<N, 128>>>(Hb, b2, N);

    // Layer 3: K=512, M=128 (heads=1)
    k_gemm_mma<<<dim3(1, rowT), 256, GSMEM>>>(Ab, W3b, Hb, a_src3, a_dst3, As3, Ad3, N, 512, 128, 1);
    k_softmax<1><<<(N + 7) / 8, 256>>>(As3, Ad3, N);
    k_aggregate<1, 32><<<N, 32>>>(Hb, b3, N);

    // MLP head
    k_fc<<<(N + FC_NB - 1) / FC_NB, 64>>>(fc1w, fc1b, fc2w, fc2b, out, N);
}

// round 15
// speedup vs baseline: 1.0511x; 1.0229x over previous
#include <cuda_runtime.h>
#include <cuda_bf16.h>
#include <cuda_fp16.h>
#include <cstdint>
#include <math.h>

// Problem constants (fixed by the dataset)
#define NMAX 50000
#define EMAX 400000
#define ETMAX (NMAX + EMAX)   // edges + self loops
#define HEADS 4
#define HID 128

// ---------------- static scratch (no allocations allowed) ----------------
__device__ __align__(16) __half g_Hbuf[(size_t)NMAX * 512];       // GEMM output h (fp16, aggregate input)
__device__ __align__(16) __nv_bfloat16 g_Abuf[(size_t)NMAX * 512];// activations bf16 (GEMM A operand)
__device__ __align__(16) float g_attn[18 * NMAX];                 // As1 Ad1 As2 Ad2 As3 Ad3 (packed)
__device__ __align__(16) float g_w[(size_t)ETMAX * HEADS];        // per-edge-per-head unnormalized weights
__device__ __align__(16) float g_rinv[NMAX * HEADS];              // per-(node,head) 1/sum
__device__ __align__(16) __nv_bfloat16 g_W1b[64 * 512];           // bf16 transposed weights [n][k]
__device__ __align__(16) __nv_bfloat16 g_W2b[512 * 512];
__device__ __align__(16) __nv_bfloat16 g_W3b[512 * 128];
__device__ int g_deg[NMAX];
__device__ int g_incl[NMAX];
__device__ int g_bsum[64];
__device__ int g_boff[64];
__device__ int g_rowptr[NMAX + 1];
__device__ int g_col[ETMAX];
__device__ int g_widx[NMAX];

// ---------------- helpers ----------------
__device__ __forceinline__ uint32_t smem_u32(const void* p) {
    uint32_t a;
    asm("{ .reg .u64 t; cvta.to.shared.u64 t, %1; cvt.u32.u64 %0, t; }" : "=r"(a) : "l"(p));
    return a;
}
__device__ __forceinline__ void ldsm4(uint32_t& r0, uint32_t& r1, uint32_t& r2, uint32_t& r3, uint32_t addr) {
    asm volatile("ldmatrix.sync.aligned.m8n8.x4.shared.b16 {%0,%1,%2,%3}, [%4];"
                 : "=r"(r0), "=r"(r1), "=r"(r2), "=r"(r3) : "r"(addr));
}
__device__ __forceinline__ void ldsm2(uint32_t& r0, uint32_t& r1, uint32_t addr) {
    asm volatile("ldmatrix.sync.aligned.m8n8.x2.shared.b16 {%0,%1}, [%2];"
                 : "=r"(r0), "=r"(r1) : "r"(addr));
}
__device__ __forceinline__ void mma_bf16(float* c, const uint32_t* a, uint32_t b0, uint32_t b1) {
    asm volatile("mma.sync.aligned.m16n8k16.row.col.f32.bf16.bf16.f32 "
                 "{%0,%1,%2,%3}, {%4,%5,%6,%7}, {%8,%9}, {%0,%1,%2,%3};"
                 : "+f"(c[0]), "+f"(c[1]), "+f"(c[2]), "+f"(c[3])
                 : "r"(a[0]), "r"(a[1]), "r"(a[2]), "r"(a[3]), "r"(b0), "r"(b1));
}
__device__ __forceinline__ void cp_async16(uint32_t dst, const void* src, int sbytes) {
    asm volatile("cp.async.cg.shared.global [%0], [%1], 16, %2;"
                 :: "r"(dst), "l"(src), "r"(sbytes) : "memory");
}
__device__ __forceinline__ void cp_commit() { asm volatile("cp.async.commit_group;" ::: "memory"); }
__device__ __forceinline__ void cp_wait1() { asm volatile("cp.async.wait_group 1;" ::: "memory"); }
__device__ __forceinline__ void cp_wait0() { asm volatile("cp.async.wait_group 0;" ::: "memory"); }

// ---------------- CSR construction ----------------
__global__ void k_count(const int* __restrict__ dst, int E) {
    int i = blockIdx.x * blockDim.x + threadIdx.x;
    if (i < E) atomicAdd(&g_deg[dst[i]], 1);
}
__global__ void k_scan1(int N) {
    __shared__ int sh[1024];
    int i = blockIdx.x * 1024 + threadIdx.x;
    int v = (i < N) ? (g_deg[i] + 1) : 0;   // +1 = self loop
    sh[threadIdx.x] = v;
    __syncthreads();
    for (int off = 1; off < 1024; off <<= 1) {
        int u = (threadIdx.x >= off) ? sh[threadIdx.x - off] : 0;
        __syncthreads();
        sh[threadIdx.x] += u;
        __syncthreads();
    }
    if (i < N) g_incl[i] = sh[threadIdx.x];
    if (threadIdx.x == 1023) g_bsum[blockIdx.x] = sh[1023];
}
__global__ void k_scan2(int nb) {
    __shared__ int sh[64];
    int t = threadIdx.x;
    int v = (t < nb) ? g_bsum[t] : 0;
    sh[t] = v;
    __syncthreads();
    for (int off = 1; off < 64; off <<= 1) {
        int u = (t >= off) ? sh[t - off] : 0;
        __syncthreads();
        sh[t] += u;
        __syncthreads();
    }
    g_boff[t] = sh[t] - v;
}
__global__ void k_scan3(int N) {
    int i = blockIdx.x * blockDim.x + threadIdx.x;
    if (i < N) {
        g_rowptr[i + 1] = g_incl[i] + g_boff[i >> 10];
        if (i == 0) g_rowptr[0] = 0;
    }
}
__global__ void k_fill_self(int N) {
    int i = blockIdx.x * blockDim.x + threadIdx.x;
    if (i < N) { g_col[g_rowptr[i]] = i; g_widx[i] = 1; }
}
__global__ void k_fill_edges(const int* __restrict__ src, const int* __restrict__ dst, int E) {
    int i = blockIdx.x * blockDim.x + threadIdx.x;
    if (i < E) {
        int d = dst[i];
        int p = atomicAdd(&g_widx[d], 1);
        g_col[g_rowptr[d] + p] = src[i];
    }
}

// ---------------- weight convert+transpose: out[n*K+k] = bf16(W[k*M+n]) ----------------
__global__ void k_wconv(const float* __restrict__ W, int K, int M,
                        __nv_bfloat16* __restrict__ ob) {
    int idx = blockIdx.x * blockDim.x + threadIdx.x;
    if (idx >= K * M) return;
    int n = idx / K, k = idx - n * K;
    ob[idx] = __float2bfloat16(W[(size_t)k * M + n]);
}

// ---------------- activation convert (layer-1 input x -> bf16) ----------------
__global__ void k_aconv(const float* __restrict__ X, int total) {
    int i = blockIdx.x * blockDim.x + threadIdx.x;
    if (i >= total) return;
    g_Abuf[i] = __float2bfloat16(X[i]);
}

// ---------------- HMMA bf16 GEMM with fused alpha epilogue ----------------
// C[N,M] (fp16) = A[N,K] @ W[K,M]; As/Ad += C_tile . a_src/a_dst (f32, per head).
#define PITCHB 80          // bytes per padded smem row (64 data + 16 pad)
#define BUFSZ  (128 * PITCHB)   // 10240 B per buffer
#define STAGESZ (2 * BUFSZ)     // A, B
__global__ void __launch_bounds__(256) k_gemm_mma(const __nv_bfloat16* __restrict__ Ab,
                                                  const __nv_bfloat16* __restrict__ Wb,
                                                  __half* __restrict__ C,
                                                  const float* __restrict__ avec_s,
                                                  const float* __restrict__ avec_d,
                                                  float* __restrict__ As,
                                                  float* __restrict__ Ad,
                                                  int N, int K, int M, int H) {
    extern __shared__ char smem[];
    uint32_t sb = smem_u32(smem);

    int tid = threadIdx.x;
    int lane = tid & 31, wid = tid >> 5;
    int wm = wid >> 2, wn = wid & 3;           // warp grid 2x4
    int row0 = blockIdx.y * 128, col0 = blockIdx.x * 128;
    int hd = blockIdx.x;                        // head index (tile width == HID)

    float acc[4][4][4];
#pragma unroll
    for (int i = 0; i < 4; i++)
#pragma unroll
        for (int j = 0; j < 4; j++)
#pragma unroll
            for (int q = 0; q < 4; q++) acc[i][j][q] = 0.f;

    int c0row = tid >> 1, c0col = (tid & 1) * 2;
    int arow_g = row0 + c0row;
    int brow_g = col0 + c0row;
    const __nv_bfloat16* apb = Ab + (size_t)arow_g * K + c0col * 8;
    const __nv_bfloat16* bpb = Wb + (size_t)brow_g * K + c0col * 8;
    int avalid = (arow_g < N) ? 16 : 0;
    uint32_t dbase = sb + c0row * PITCHB + c0col * 16;

    int a_row = wm * 64 + (lane & 15);
    int a_kp = (lane >> 4) * 8;
    int b_row = wn * 32 + (lane & 7);
    int b_kp = ((lane >> 3) & 1) * 8;

    int nch = K >> 5;

    {
#pragma unroll
        for (int b = 0; b < 2; b++) {
            uint32_t d = dbase + b * 16;
            cp_async16(d,         apb + b * 8, avalid);
            cp_async16(d + BUFSZ, bpb + b * 8, 16);
        }
        cp_commit();
    }

    for (int ch = 0; ch < nch; ch++) {
        if (ch + 1 < nch) {
            int koff = (ch + 1) * 32;
            uint32_t sdst = dbase + ((ch + 1) & 1) * STAGESZ;
#pragma unroll
            for (int b = 0; b < 2; b++) {
                uint32_t d = sdst + b * 16;
                cp_async16(d,         apb + koff + b * 8, avalid);
                cp_async16(d + BUFSZ, bpb + koff + b * 8, 16);
            }
            cp_commit();
            cp_wait1();
        } else {
            cp_wait0();
        }
        __syncthreads();

        uint32_t st = sb + (ch & 1) * STAGESZ;
#pragma unroll
        for (int kk = 0; kk < 32; kk += 16) {
            uint32_t av[4][4];
#pragma unroll
            for (int i = 0; i < 4; i++) {
                uint32_t off = (a_row + i * 16) * PITCHB + (kk + a_kp) * 2;
                ldsm4(av[i][0], av[i][1], av[i][2], av[i][3], st + off);
            }
#pragma unroll
            for (int j = 0; j < 4; j++) {
                uint32_t boff = (b_row + j * 8) * PITCHB + (kk + b_kp) * 2;
                uint32_t b0, b1;
                ldsm2(b0, b1, st + BUFSZ + boff);
#pragma unroll
                for (int i = 0; i < 4; i++) {
                    mma_bf16(acc[i][j], av[i], b0, b1);
                }
            }
        }
        __syncthreads();
    }

    // --- epilogue: write C (fp16) + fused alpha partial dots (f32) ---
    int crow = row0 + wm * 64 + (lane >> 2);
    int ccol_l = wn * 32 + (lane & 3) * 2;
    float as0[4], as1[4], ad0[4], ad1[4];
#pragma unroll
    for (int j = 0; j < 4; j++) {
        int c = hd * HID + ccol_l + j * 8;
        as0[j] = avec_s[c]; as1[j] = avec_s[c + 1];
        ad0[j] = avec_d[c]; ad1[j] = avec_d[c + 1];
    }
#pragma unroll
    for (int i = 0; i < 4; i++) {
        int r1 = crow + i * 16, r2 = r1 + 8;
        float s1 = 0.f, s2 = 0.f, d1 = 0.f, d2 = 0.f;
#pragma unroll
        for (int j = 0; j < 4; j++) {
            int cc = col0 + ccol_l + j * 8;
            if (r1 < N) *(__half2*)(C + (size_t)r1 * M + cc) = __floats2half2_rn(acc[i][j][0], acc[i][j][1]);
            if (r2 < N) *(__half2*)(C + (size_t)r2 * M + cc) = __floats2half2_rn(acc[i][j][2], acc[i][j][3]);
            s1 = fmaf(acc[i][j][0], as0[j], fmaf(acc[i][j][1], as1[j], s1));
            d1 = fmaf(acc[i][j][0], ad0[j], fmaf(acc[i][j][1], ad1[j], d1));
            s2 = fmaf(acc[i][j][2], as0[j], fmaf(acc[i][j][3], as1[j], s2));
            d2 = fmaf(acc[i][j][2], ad0[j], fmaf(acc[i][j][3], ad1[j], d2));
        }
#pragma unroll
        for (int off = 1; off < 4; off <<= 1) {
            s1 += __shfl_xor_sync(0xffffffffu, s1, off);
            s2 += __shfl_xor_sync(0xffffffffu, s2, off);
            d1 += __shfl_xor_sync(0xffffffffu, d1, off);
            d2 += __shfl_xor_sync(0xffffffffu, d2, off);
        }
        if ((lane & 3) == 0) {
            if (r1 < N) { atomicAdd(&As[r1 * H + hd], s1); atomicAdd(&Ad[r1 * H + hd], d1); }
            if (r2 < N) { atomicAdd(&As[r2 * H + hd], s2); atomicAdd(&Ad[r2 * H + hd], d2); }
        }
    }
}

// ---------------- per-node segment softmax (2 passes; stores unnormalized + rinv) ----------------
template <int H>
__global__ void k_softmax(const float* __restrict__ As, const float* __restrict__ Ad, int N) {
    int n = blockIdx.x * (blockDim.x >> 5) + (threadIdx.x >> 5);
    int lane = threadIdx.x & 31;
    if (n >= N) return;
    int beg = g_rowptr[n], end = g_rowptr[n + 1];
    float adh[H], mx[H], sm[H];
#pragma unroll
    for (int h = 0; h < H; h++) {
        adh[h] = Ad[n * H + h];
        mx[h] = -1e30f;
        sm[h] = 0.f;
    }
    for (int j = beg + lane; j < end; j += 32) {
        int s = g_col[j];
#pragma unroll
        for (int h = 0; h < H; h++) {
            float e = As[s * H + h] + adh[h];
            e = e > 0.f ? e : 0.2f * e;           // leaky relu
            g_w[(size_t)j * H + h] = e;
            mx[h] = fmaxf(mx[h], e);
        }
    }
#pragma unroll
    for (int h = 0; h < H; h++)
        for (int off = 16; off; off >>= 1)
            mx[h] = fmaxf(mx[h], __shfl_xor_sync(0xffffffffu, mx[h], off));
    for (int j = beg + lane; j < end; j += 32) {
#pragma unroll
        for (int h = 0; h < H; h++) {
            float ex = __expf(g_w[(size_t)j * H + h] - mx[h]);
            g_w[(size_t)j * H + h] = ex;          // unnormalized
            sm[h] += ex;
        }
    }
#pragma unroll
    for (int h = 0; h < H; h++) {
        for (int off = 16; off; off >>= 1)
            sm[h] += __shfl_xor_sync(0xffffffffu, sm[h], off);
    }
    if (lane == 0) {
#pragma unroll
        for (int h = 0; h < H; h++) g_rinv[n * H + h] = 1.f / sm[h];
    }
}

// ---------------- per-node weighted gather-aggregate + rinv scale + bias + elu -> bf16 ----------------
// NT threads; thread t covers cols 4t..4t+3 (4 fp16 = one 8B load), within one head.
template <int H, int NT>
__global__ __launch_bounds__(NT) void k_aggregate(const __half* __restrict__ hbuf,
                                                  const float* __restrict__ bias,
                                                  int N) {
    int n = blockIdx.x;
    if (n >= N) return;
    int t = threadIdx.x;
    int hd = (H == 4) ? (t >> 5) : 0;
    float4 acc = make_float4(0.f, 0.f, 0.f, 0.f);
    int beg = g_rowptr[n], end = g_rowptr[n + 1];
#pragma unroll 2
    for (int j = beg; j < end; j++) {
        int s = g_col[j];
        float w = g_w[(size_t)j * H + hd];
        uint2 u = ((const uint2*)(hbuf + (size_t)s * (H * HID)))[t];
        float2 f0 = __half22float2(*(__half2*)&u.x);
        float2 f1 = __half22float2(*(__half2*)&u.y);
        acc.x = fmaf(w, f0.x, acc.x);
        acc.y = fmaf(w, f0.y, acc.y);
        acc.z = fmaf(w, f1.x, acc.z);
        acc.w = fmaf(w, f1.y, acc.w);
    }
    float rinv = g_rinv[n * H + hd];
    float4 bv = ((const float4*)bias)[t];
    float o[4] = {fmaf(acc.x, rinv, bv.x), fmaf(acc.y, rinv, bv.y),
                  fmaf(acc.z, rinv, bv.z), fmaf(acc.w, rinv, bv.w)};
    ushort hi[4];
#pragma unroll
    for (int q = 0; q < 4; q++) {
        float v = o[q] > 0.f ? o[q] : (__expf(o[q]) - 1.f);   // elu
        hi[q] = __bfloat16_as_ushort(__float2bfloat16(v));
    }
    size_t o4 = (size_t)n * (H * HID) + 4 * t;
    *(uint2*)(g_Abuf + o4) = make_uint2((uint32_t)hi[0] | ((uint32_t)hi[1] << 16),
                                        (uint32_t)hi[2] | ((uint32_t)hi[3] << 16));
}

// ---------------- fc head: 16 nodes per 64-thread block (w1 L1-resident) ----------------
#define FC_NB 16
__global__ __launch_bounds__(64) void k_fc(const float* __restrict__ w1,
                                           const float* __restrict__ b1,
                                           const float* __restrict__ w2,
                                           const float* __restrict__ b2,
                                           float* __restrict__ out, int N) {
    __shared__ float xs[128];
    __shared__ float part[2];
    int t = threadIdx.x;   // 64
    float bias1 = b1[t];
    float wv2 = w2[t];
    float bias2 = b2[0];
    for (int it = 0; it < FC_NB; it++) {
        int n = blockIdx.x * FC_NB + it;
        if (n >= N) return;
        size_t base = (size_t)n * 128;
        xs[t]      = __bfloat162float(g_Abuf[base + t]);
        xs[t + 64] = __bfloat162float(g_Abuf[base + t + 64]);
        __syncthreads();
        float d0 = bias1, d1 = 0.f;
#pragma unroll 8
        for (int k = 0; k < 128; k += 2) {
            d0 = fmaf(xs[k],     w1[k * 64 + t],       d0);
            d1 = fmaf(xs[k + 1], w1[(k + 1) * 64 + t], d1);
        }
        float d = fmaxf(d0 + d1, 0.f);
        float p = d * wv2;
        for (int off = 16; off; off >>= 1) p += __shfl_xor_sync(0xffffffffu, p, off);
        if ((t & 31) == 0) part[t >> 5] = p;
        __syncthreads();
        if (t == 0) out[n] = 1.f / (1.f + __expf(-(part[0] + part[1] + bias2)));
        __syncthreads();
    }
}

// ---------------- launch ----------------
extern "C" void kernel_launch(void* const* d_in, const int* in_sizes, int n_in,
                              void* d_out, int out_size) {
    const float* x      = (const float*)d_in[0];
    const int*   eidx   = (const int*)d_in[1];
    const float* W1     = (const float*)d_in[2];
    const float* a_src1 = (const float*)d_in[3];
    const float* a_dst1 = (const float*)d_in[4];
    const float* b1     = (const float*)d_in[5];
    const float* W2     = (const float*)d_in[6];
    const float* a_src2 = (const float*)d_in[7];
    const float* a_dst2 = (const float*)d_in[8];
    const float* b2     = (const float*)d_in[9];
    const float* W3     = (const float*)d_in[10];
    const float* a_src3 = (const float*)d_in[11];
    const float* a_dst3 = (const float*)d_in[12];
    const float* b3     = (const float*)d_in[13];
    const float* fc1w   = (const float*)d_in[14];
    const float* fc1b   = (const float*)d_in[15];
    const float* fc2w   = (const float*)d_in[16];
    const float* fc2b   = (const float*)d_in[17];
    float* out = (float*)d_out;

    int N = in_sizes[0] / 64;
    int E = in_sizes[1] / 2;
    const int* srcp = eidx;
    const int* dstp = eidx + E;

    float* attn;
    __half* Hb;
    int* degp;
    __nv_bfloat16 *W1b, *W2b, *W3b, *Ab;
    cudaGetSymbolAddress((void**)&Hb, g_Hbuf);
    cudaGetSymbolAddress((void**)&attn, g_attn);
    cudaGetSymbolAddress((void**)&degp, g_deg);
    cudaGetSymbolAddress((void**)&W1b, g_W1b);
    cudaGetSymbolAddress((void**)&W2b, g_W2b);
    cudaGetSymbolAddress((void**)&W3b, g_W3b);
    cudaGetSymbolAddress((void**)&Ab, g_Abuf);

    float* As1 = attn;
    float* Ad1 = attn + 4 * NMAX;
    float* As2 = attn + 8 * NMAX;
    float* Ad2 = attn + 12 * NMAX;
    float* As3 = attn + 16 * NMAX;
    float* Ad3 = attn + 17 * NMAX;

    const int GSMEM = 2 * STAGESZ;   // 40960
    static int s_init = 0;
    static cudaStream_t s1;
    static cudaEvent_t e_fork, e_join;
    if (!s_init) {
        cudaFuncSetAttribute(k_gemm_mma, cudaFuncAttributeMaxDynamicSharedMemorySize, GSMEM);
        cudaStreamCreateWithFlags(&s1, cudaStreamNonBlocking);
        cudaEventCreateWithFlags(&e_fork, cudaEventDisableTiming);
        cudaEventCreateWithFlags(&e_join, cudaEventDisableTiming);
        s_init = 1;
    }

    int nb = (N + 1023) / 1024;
    int rowT = (N + 127) / 128;

    // ---- fork: CSR branch + W2/W3 converts on s1, concurrent with main chain ----
    cudaEventRecord(e_fork, 0);
    cudaStreamWaitEvent(s1, e_fork, 0);
    cudaMemsetAsync(degp, 0, N * sizeof(int), s1);
    k_count<<<(E + 255) / 256, 256, 0, s1>>>(dstp, E);
    k_scan1<<<nb, 1024, 0, s1>>>(N);
    k_scan2<<<1, 64, 0, s1>>>(nb);
    k_scan3<<<(N + 255) / 256, 256, 0, s1>>>(N);
    k_fill_self<<<(N + 255) / 256, 256, 0, s1>>>(N);
    k_fill_edges<<<(E + 255) / 256, 256, 0, s1>>>(srcp, dstp, E);
    k_wconv<<<(512 * 512 + 255) / 256, 256, 0, s1>>>(W2, 512, 512, W2b);
    k_wconv<<<(512 * 128 + 255) / 256, 256, 0, s1>>>(W3, 512, 128, W3b);
    cudaEventRecord(e_join, s1);

    // ---- main chain: layer-1 GEMM prerequisites + GEMM ----
    cudaMemsetAsync(attn, 0, 18 * NMAX * sizeof(float));
    k_aconv<<<(N * 64 + 255) / 256, 256>>>(x, N * 64);
    k_wconv<<<(64 * 512 + 255) / 256, 256>>>(W1, 64, 512, W1b);
    k_gemm_mma<<<dim3(4, rowT), 256, GSMEM>>>(Ab, W1b, Hb, a_src1, a_dst1, As1, Ad1, N, 64, 512, 4);

    // ---- join: need CSR + W2/W3 converts from here on ----
    cudaStreamWaitEvent(0, e_join, 0);

    k_softmax<4><<<(N + 7) / 8, 256>>>(As1, Ad1, N);
    k_aggregate<4, 128><<<N, 128>>>(Hb, b1, N);

    // Layer 2: K=512, M=512
    k_gemm_mma<<<dim3(4, rowT), 256, GSMEM>>>(Ab, W2b, Hb, a_src2, a_dst2, As2, Ad2, N, 512, 512, 4);
    k_softmax<4><<<(N + 7) / 8, 256>>>(As2, Ad2, N);
    k_aggregate<4, 128><<<N, 128>>>(Hb, b2, N);

    // Layer 3: K=512, M=128 (heads=1)
    k_gemm_mma<<<dim3(1, rowT), 256, GSMEM>>>(Ab, W3b, Hb, a_src3, a_dst3, As3, Ad3, N, 512, 128, 1);
    k_softmax<1><<<(N + 7) / 8, 256>>>(As3, Ad3, N);
    k_aggregate<1, 32><<<N, 32>>>(Hb, b3, N);

    // MLP head
    k_fc<<<(N + FC_NB - 1) / FC_NB, 64>>>(fc1w, fc1b, fc2w, fc2b, out, N);
}

// round 16
// speedup vs baseline: 1.0566x; 1.0052x over previous
#include <cuda_runtime.h>
#include <cuda_bf16.h>
#include <cuda_fp16.h>
#include <cstdint>
#include <math.h>

// Problem constants (fixed by the dataset)
#define NMAX 50000
#define EMAX 400000
#define ETMAX (NMAX + EMAX)   // edges + self loops
#define HEADS 4
#define HID 128

// ---------------- static scratch (no allocations allowed) ----------------
__device__ __align__(16) __half g_Hbuf[(size_t)NMAX * 512];       // GEMM output h (fp16, aggregate input)
__device__ __align__(16) __nv_bfloat16 g_Abuf[(size_t)NMAX * 512];// activations bf16 (GEMM A operand)
__device__ __align__(16) float g_attn[18 * NMAX];                 // As1 Ad1 As2 Ad2 As3 Ad3 (packed)
__device__ __align__(16) float g_w[(size_t)ETMAX * HEADS];        // per-edge-per-head unnormalized weights
__device__ __align__(16) float g_rinv[NMAX * HEADS];              // per-(node,head) 1/sum
__device__ __align__(16) __nv_bfloat16 g_W1b[64 * 512];           // bf16 transposed weights [n][k]
__device__ __align__(16) __nv_bfloat16 g_W2b[512 * 512];
__device__ __align__(16) __nv_bfloat16 g_W3b[512 * 128];
__device__ int g_deg[NMAX];
__device__ int g_incl[NMAX];
__device__ int g_bsum[64];
__device__ int g_boff[64];
__device__ int g_rowptr[NMAX + 1];
__device__ int g_col[ETMAX];
__device__ int g_widx[NMAX];

// ---------------- helpers ----------------
__device__ __forceinline__ uint32_t smem_u32(const void* p) {
    uint32_t a;
    asm("{ .reg .u64 t; cvta.to.shared.u64 t, %1; cvt.u32.u64 %0, t; }" : "=r"(a) : "l"(p));
    return a;
}
__device__ __forceinline__ void ldsm4(uint32_t& r0, uint32_t& r1, uint32_t& r2, uint32_t& r3, uint32_t addr) {
    asm volatile("ldmatrix.sync.aligned.m8n8.x4.shared.b16 {%0,%1,%2,%3}, [%4];"
                 : "=r"(r0), "=r"(r1), "=r"(r2), "=r"(r3) : "r"(addr));
}
__device__ __forceinline__ void ldsm2(uint32_t& r0, uint32_t& r1, uint32_t addr) {
    asm volatile("ldmatrix.sync.aligned.m8n8.x2.shared.b16 {%0,%1}, [%2];"
                 : "=r"(r0), "=r"(r1) : "r"(addr));
}
__device__ __forceinline__ void mma_bf16(float* c, const uint32_t* a, uint32_t b0, uint32_t b1) {
    asm volatile("mma.sync.aligned.m16n8k16.row.col.f32.bf16.bf16.f32 "
                 "{%0,%1,%2,%3}, {%4,%5,%6,%7}, {%8,%9}, {%0,%1,%2,%3};"
                 : "+f"(c[0]), "+f"(c[1]), "+f"(c[2]), "+f"(c[3])
                 : "r"(a[0]), "r"(a[1]), "r"(a[2]), "r"(a[3]), "r"(b0), "r"(b1));
}
__device__ __forceinline__ void cp_async16(uint32_t dst, const void* src, int sbytes) {
    asm volatile("cp.async.cg.shared.global [%0], [%1], 16, %2;"
                 :: "r"(dst), "l"(src), "r"(sbytes) : "memory");
}
__device__ __forceinline__ void cp_commit() { asm volatile("cp.async.commit_group;" ::: "memory"); }
__device__ __forceinline__ void cp_wait1() { asm volatile("cp.async.wait_group 1;" ::: "memory"); }
__device__ __forceinline__ void cp_wait0() { asm volatile("cp.async.wait_group 0;" ::: "memory"); }

// ---------------- CSR construction ----------------
__global__ void k_count(const int* __restrict__ dst, int E) {
    int i = blockIdx.x * blockDim.x + threadIdx.x;
    if (i < E) atomicAdd(&g_deg[dst[i]], 1);
}
__global__ void k_scan1(int N) {
    __shared__ int sh[1024];
    int i = blockIdx.x * 1024 + threadIdx.x;
    int v = (i < N) ? (g_deg[i] + 1) : 0;   // +1 = self loop
    sh[threadIdx.x] = v;
    __syncthreads();
    for (int off = 1; off < 1024; off <<= 1) {
        int u = (threadIdx.x >= off) ? sh[threadIdx.x - off] : 0;
        __syncthreads();
        sh[threadIdx.x] += u;
        __syncthreads();
    }
    if (i < N) g_incl[i] = sh[threadIdx.x];
    if (threadIdx.x == 1023) g_bsum[blockIdx.x] = sh[1023];
}
__global__ void k_scan2(int nb) {
    __shared__ int sh[64];
    int t = threadIdx.x;
    int v = (t < nb) ? g_bsum[t] : 0;
    sh[t] = v;
    __syncthreads();
    for (int off = 1; off < 64; off <<= 1) {
        int u = (t >= off) ? sh[t - off] : 0;
        __syncthreads();
        sh[t] += u;
        __syncthreads();
    }
    g_boff[t] = sh[t] - v;
}
__global__ void k_scan3(int N) {
    int i = blockIdx.x * blockDim.x + threadIdx.x;
    if (i < N) {
        g_rowptr[i + 1] = g_incl[i] + g_boff[i >> 10];
        if (i == 0) g_rowptr[0] = 0;
    }
}
__global__ void k_fill_self(int N) {
    int i = blockIdx.x * blockDim.x + threadIdx.x;
    if (i < N) { g_col[g_rowptr[i]] = i; g_widx[i] = 1; }
}
__global__ void k_fill_edges(const int* __restrict__ src, const int* __restrict__ dst, int E) {
    int i = blockIdx.x * blockDim.x + threadIdx.x;
    if (i < E) {
        int d = dst[i];
        int p = atomicAdd(&g_widx[d], 1);
        g_col[g_rowptr[d] + p] = src[i];
    }
}

// ---------------- weight convert+transpose: out[n*K+k] = bf16(W[k*M+n]) ----------------
__global__ void k_wconv(const float* __restrict__ W, int K, int M,
                        __nv_bfloat16* __restrict__ ob) {
    int idx = blockIdx.x * blockDim.x + threadIdx.x;
    if (idx >= K * M) return;
    int n = idx / K, k = idx - n * K;
    ob[idx] = __float2bfloat16(W[(size_t)k * M + n]);
}

// ---------------- activation convert (layer-1 input x -> bf16) ----------------
__global__ void k_aconv(const float* __restrict__ X, int total) {
    int i = blockIdx.x * blockDim.x + threadIdx.x;
    if (i >= total) return;
    g_Abuf[i] = __float2bfloat16(X[i]);
}

// ---------------- HMMA bf16 GEMM with fused alpha epilogue ----------------
// C[N,M] (fp16) = A[N,K] @ W[K,M]; As/Ad += C_tile . a_src/a_dst (f32, per head).
#define PITCHB 80          // bytes per padded smem row (64 data + 16 pad)
#define BUFSZ  (128 * PITCHB)   // 10240 B per buffer
#define STAGESZ (2 * BUFSZ)     // A, B
__global__ void __launch_bounds__(256) k_gemm_mma(const __nv_bfloat16* __restrict__ Ab,
                                                  const __nv_bfloat16* __restrict__ Wb,
                                                  __half* __restrict__ C,
                                                  const float* __restrict__ avec_s,
                                                  const float* __restrict__ avec_d,
                                                  float* __restrict__ As,
                                                  float* __restrict__ Ad,
                                                  int N, int K, int M, int H) {
    extern __shared__ char smem[];
    uint32_t sb = smem_u32(smem);

    int tid = threadIdx.x;
    int lane = tid & 31, wid = tid >> 5;
    int wm = wid >> 2, wn = wid & 3;           // warp grid 2x4
    int row0 = blockIdx.y * 128, col0 = blockIdx.x * 128;
    int hd = blockIdx.x;                        // head index (tile width == HID)

    float acc[4][4][4];
#pragma unroll
    for (int i = 0; i < 4; i++)
#pragma unroll
        for (int j = 0; j < 4; j++)
#pragma unroll
            for (int q = 0; q < 4; q++) acc[i][j][q] = 0.f;

    int c0row = tid >> 1, c0col = (tid & 1) * 2;
    int arow_g = row0 + c0row;
    int brow_g = col0 + c0row;
    const __nv_bfloat16* apb = Ab + (size_t)arow_g * K + c0col * 8;
    const __nv_bfloat16* bpb = Wb + (size_t)brow_g * K + c0col * 8;
    int avalid = (arow_g < N) ? 16 : 0;
    uint32_t dbase = sb + c0row * PITCHB + c0col * 16;

    int a_row = wm * 64 + (lane & 15);
    int a_kp = (lane >> 4) * 8;
    int b_row = wn * 32 + (lane & 7);
    int b_kp = ((lane >> 3) & 1) * 8;

    int nch = K >> 5;

    {
#pragma unroll
        for (int b = 0; b < 2; b++) {
            uint32_t d = dbase + b * 16;
            cp_async16(d,         apb + b * 8, avalid);
            cp_async16(d + BUFSZ, bpb + b * 8, 16);
        }
        cp_commit();
    }

    for (int ch = 0; ch < nch; ch++) {
        if (ch + 1 < nch) {
            int koff = (ch + 1) * 32;
            uint32_t sdst = dbase + ((ch + 1) & 1) * STAGESZ;
#pragma unroll
            for (int b = 0; b < 2; b++) {
                uint32_t d = sdst + b * 16;
                cp_async16(d,         apb + koff + b * 8, avalid);
                cp_async16(d + BUFSZ, bpb + koff + b * 8, 16);
            }
            cp_commit();
            cp_wait1();
        } else {
            cp_wait0();
        }
        __syncthreads();

        uint32_t st = sb + (ch & 1) * STAGESZ;
#pragma unroll
        for (int kk = 0; kk < 32; kk += 16) {
            uint32_t av[4][4];
#pragma unroll
            for (int i = 0; i < 4; i++) {
                uint32_t off = (a_row + i * 16) * PITCHB + (kk + a_kp) * 2;
                ldsm4(av[i][0], av[i][1], av[i][2], av[i][3], st + off);
            }
#pragma unroll
            for (int j = 0; j < 4; j++) {
                uint32_t boff = (b_row + j * 8) * PITCHB + (kk + b_kp) * 2;
                uint32_t b0, b1;
                ldsm2(b0, b1, st + BUFSZ + boff);
#pragma unroll
                for (int i = 0; i < 4; i++) {
                    mma_bf16(acc[i][j], av[i], b0, b1);
                }
            }
        }
        __syncthreads();
    }

    // --- epilogue: write C (fp16) + fused alpha partial dots (f32) ---
    int crow = row0 + wm * 64 + (lane >> 2);
    int ccol_l = wn * 32 + (lane & 3) * 2;
    float as0[4], as1[4], ad0[4], ad1[4];
#pragma unroll
    for (int j = 0; j < 4; j++) {
        int c = hd * HID + ccol_l + j * 8;
        as0[j] = avec_s[c]; as1[j] = avec_s[c + 1];
        ad0[j] = avec_d[c]; ad1[j] = avec_d[c + 1];
    }
#pragma unroll
    for (int i = 0; i < 4; i++) {
        int r1 = crow + i * 16, r2 = r1 + 8;
        float s1 = 0.f, s2 = 0.f, d1 = 0.f, d2 = 0.f;
#pragma unroll
        for (int j = 0; j < 4; j++) {
            int cc = col0 + ccol_l + j * 8;
            if (r1 < N) *(__half2*)(C + (size_t)r1 * M + cc) = __floats2half2_rn(acc[i][j][0], acc[i][j][1]);
            if (r2 < N) *(__half2*)(C + (size_t)r2 * M + cc) = __floats2half2_rn(acc[i][j][2], acc[i][j][3]);
            s1 = fmaf(acc[i][j][0], as0[j], fmaf(acc[i][j][1], as1[j], s1));
            d1 = fmaf(acc[i][j][0], ad0[j], fmaf(acc[i][j][1], ad1[j], d1));
            s2 = fmaf(acc[i][j][2], as0[j], fmaf(acc[i][j][3], as1[j], s2));
            d2 = fmaf(acc[i][j][2], ad0[j], fmaf(acc[i][j][3], ad1[j], d2));
        }
#pragma unroll
        for (int off = 1; off < 4; off <<= 1) {
            s1 += __shfl_xor_sync(0xffffffffu, s1, off);
            s2 += __shfl_xor_sync(0xffffffffu, s2, off);
            d1 += __shfl_xor_sync(0xffffffffu, d1, off);
            d2 += __shfl_xor_sync(0xffffffffu, d2, off);
        }
        if ((lane & 3) == 0) {
            if (r1 < N) { atomicAdd(&As[r1 * H + hd], s1); atomicAdd(&Ad[r1 * H + hd], d1); }
            if (r2 < N) { atomicAdd(&As[r2 * H + hd], s2); atomicAdd(&Ad[r2 * H + hd], d2); }
        }
    }
}

// ---------------- per-node segment softmax (vectorized float4 for H=4) ----------------
__device__ __forceinline__ float lrelu(float e) { return e > 0.f ? e : 0.2f * e; }

template <int H>
__global__ void k_softmax(const float* __restrict__ As, const float* __restrict__ Ad, int N) {
    int n = blockIdx.x * (blockDim.x >> 5) + (threadIdx.x >> 5);
    int lane = threadIdx.x & 31;
    if (n >= N) return;
    int beg = g_rowptr[n], end = g_rowptr[n + 1];
    if (H == 4) {
        float4 adv = *(const float4*)(Ad + n * 4);
        float4 mx = make_float4(-1e30f, -1e30f, -1e30f, -1e30f);
        float4 sm = make_float4(0.f, 0.f, 0.f, 0.f);
        for (int j = beg + lane; j < end; j += 32) {
            int s = g_col[j];
            float4 asv = *(const float4*)(As + s * 4);
            float4 e = make_float4(lrelu(asv.x + adv.x), lrelu(asv.y + adv.y),
                                   lrelu(asv.z + adv.z), lrelu(asv.w + adv.w));
            *(float4*)(g_w + (size_t)j * 4) = e;
            mx.x = fmaxf(mx.x, e.x); mx.y = fmaxf(mx.y, e.y);
            mx.z = fmaxf(mx.z, e.z); mx.w = fmaxf(mx.w, e.w);
        }
#pragma unroll
        for (int off = 16; off; off >>= 1) {
            mx.x = fmaxf(mx.x, __shfl_xor_sync(0xffffffffu, mx.x, off));
            mx.y = fmaxf(mx.y, __shfl_xor_sync(0xffffffffu, mx.y, off));
            mx.z = fmaxf(mx.z, __shfl_xor_sync(0xffffffffu, mx.z, off));
            mx.w = fmaxf(mx.w, __shfl_xor_sync(0xffffffffu, mx.w, off));
        }
        for (int j = beg + lane; j < end; j += 32) {
            float4 e = *(const float4*)(g_w + (size_t)j * 4);
            float4 ex = make_float4(__expf(e.x - mx.x), __expf(e.y - mx.y),
                                    __expf(e.z - mx.z), __expf(e.w - mx.w));
            *(float4*)(g_w + (size_t)j * 4) = ex;    // unnormalized
            sm.x += ex.x; sm.y += ex.y; sm.z += ex.z; sm.w += ex.w;
        }
#pragma unroll
        for (int off = 16; off; off >>= 1) {
            sm.x += __shfl_xor_sync(0xffffffffu, sm.x, off);
            sm.y += __shfl_xor_sync(0xffffffffu, sm.y, off);
            sm.z += __shfl_xor_sync(0xffffffffu, sm.z, off);
            sm.w += __shfl_xor_sync(0xffffffffu, sm.w, off);
        }
        if (lane == 0) {
            *(float4*)(g_rinv + n * 4) = make_float4(1.f / sm.x, 1.f / sm.y, 1.f / sm.z, 1.f / sm.w);
        }
    } else {
        float adh = Ad[n];
        float mx = -1e30f, sm = 0.f;
        for (int j = beg + lane; j < end; j += 32) {
            float e = lrelu(As[g_col[j]] + adh);
            g_w[j] = e;
            mx = fmaxf(mx, e);
        }
#pragma unroll
        for (int off = 16; off; off >>= 1) mx = fmaxf(mx, __shfl_xor_sync(0xffffffffu, mx, off));
        for (int j = beg + lane; j < end; j += 32) {
            float ex = __expf(g_w[j] - mx);
            g_w[j] = ex;
            sm += ex;
        }
#pragma unroll
        for (int off = 16; off; off >>= 1) sm += __shfl_xor_sync(0xffffffffu, sm, off);
        if (lane == 0) g_rinv[n] = 1.f / sm;
    }
}

// ---------------- per-node weighted gather-aggregate + rinv scale + bias + elu -> bf16 ----------------
// NT threads; thread t covers cols 4t..4t+3 (4 fp16 = one 8B load), within one head.
template <int H, int NT>
__global__ __launch_bounds__(NT) void k_aggregate(const __half* __restrict__ hbuf,
                                                  const float* __restrict__ bias,
                                                  int N) {
    int n = blockIdx.x;
    if (n >= N) return;
    int t = threadIdx.x;
    int hd = (H == 4) ? (t >> 5) : 0;
    float4 acc = make_float4(0.f, 0.f, 0.f, 0.f);
    int beg = g_rowptr[n], end = g_rowptr[n + 1];
#pragma unroll 2
    for (int j = beg; j < end; j++) {
        int s = g_col[j];
        float w = g_w[(size_t)j * H + hd];
        uint2 u = ((const uint2*)(hbuf + (size_t)s * (H * HID)))[t];
        float2 f0 = __half22float2(*(__half2*)&u.x);
        float2 f1 = __half22float2(*(__half2*)&u.y);
        acc.x = fmaf(w, f0.x, acc.x);
        acc.y = fmaf(w, f0.y, acc.y);
        acc.z = fmaf(w, f1.x, acc.z);
        acc.w = fmaf(w, f1.y, acc.w);
    }
    float rinv = g_rinv[n * H + hd];
    float4 bv = ((const float4*)bias)[t];
    float o[4] = {fmaf(acc.x, rinv, bv.x), fmaf(acc.y, rinv, bv.y),
                  fmaf(acc.z, rinv, bv.z), fmaf(acc.w, rinv, bv.w)};
    ushort hi[4];
#pragma unroll
    for (int q = 0; q < 4; q++) {
        float v = o[q] > 0.f ? o[q] : (__expf(o[q]) - 1.f);   // elu
        hi[q] = __bfloat16_as_ushort(__float2bfloat16(v));
    }
    size_t o4 = (size_t)n * (H * HID) + 4 * t;
    *(uint2*)(g_Abuf + o4) = make_uint2((uint32_t)hi[0] | ((uint32_t)hi[1] << 16),
                                        (uint32_t)hi[2] | ((uint32_t)hi[3] << 16));
}

// ---------------- fc head: 16 nodes per 64-thread block (w1 L1-resident) ----------------
#define FC_NB 16
__global__ __launch_bounds__(64) void k_fc(const float* __restrict__ w1,
                                           const float* __restrict__ b1,
                                           const float* __restrict__ w2,
                                           const float* __restrict__ b2,
                                           float* __restrict__ out, int N) {
    __shared__ float xs[128];
    __shared__ float part[2];
    int t = threadIdx.x;   // 64
    float bias1 = b1[t];
    float wv2 = w2[t];
    float bias2 = b2[0];
    for (int it = 0; it < FC_NB; it++) {
        int n = blockIdx.x * FC_NB + it;
        if (n >= N) return;
        size_t base = (size_t)n * 128;
        xs[t]      = __bfloat162float(g_Abuf[base + t]);
        xs[t + 64] = __bfloat162float(g_Abuf[base + t + 64]);
        __syncthreads();
        float d0 = bias1, d1 = 0.f;
#pragma unroll 8
        for (int k = 0; k < 128; k += 2) {
            d0 = fmaf(xs[k],     w1[k * 64 + t],       d0);
            d1 = fmaf(xs[k + 1], w1[(k + 1) * 64 + t], d1);
        }
        float d = fmaxf(d0 + d1, 0.f);
        float p = d * wv2;
        for (int off = 16; off; off >>= 1) p += __shfl_xor_sync(0xffffffffu, p, off);
        if ((t & 31) == 0) part[t >> 5] = p;
        __syncthreads();
        if (t == 0) out[n] = 1.f / (1.f + __expf(-(part[0] + part[1] + bias2)));
        __syncthreads();
    }
}

// ---------------- launch ----------------
extern "C" void kernel_launch(void* const* d_in, const int* in_sizes, int n_in,
                              void* d_out, int out_size) {
    const float* x      = (const float*)d_in[0];
    const int*   eidx   = (const int*)d_in[1];
    const float* W1     = (const float*)d_in[2];
    const float* a_src1 = (const float*)d_in[3];
    const float* a_dst1 = (const float*)d_in[4];
    const float* b1     = (const float*)d_in[5];
    const float* W2     = (const float*)d_in[6];
    const float* a_src2 = (const float*)d_in[7];
    const float* a_dst2 = (const float*)d_in[8];
    const float* b2     = (const float*)d_in[9];
    const float* W3     = (const float*)d_in[10];
    const float* a_src3 = (const float*)d_in[11];
    const float* a_dst3 = (const float*)d_in[12];
    const float* b3     = (const float*)d_in[13];
    const float* fc1w   = (const float*)d_in[14];
    const float* fc1b   = (const float*)d_in[15];
    const float* fc2w   = (const float*)d_in[16];
    const float* fc2b   = (const float*)d_in[17];
    float* out = (float*)d_out;

    int N = in_sizes[0] / 64;
    int E = in_sizes[1] / 2;
    const int* srcp = eidx;
    const int* dstp = eidx + E;

    float* attn;
    __half* Hb;
    int* degp;
    __nv_bfloat16 *W1b, *W2b, *W3b, *Ab;
    cudaGetSymbolAddress((void**)&Hb, g_Hbuf);
    cudaGetSymbolAddress((void**)&attn, g_attn);
    cudaGetSymbolAddress((void**)&degp, g_deg);
    cudaGetSymbolAddress((void**)&W1b, g_W1b);
    cudaGetSymbolAddress((void**)&W2b, g_W2b);
    cudaGetSymbolAddress((void**)&W3b, g_W3b);
    cudaGetSymbolAddress((void**)&Ab, g_Abuf);

    float* As1 = attn;
    float* Ad1 = attn + 4 * NMAX;
    float* As2 = attn + 8 * NMAX;
    float* Ad2 = attn + 12 * NMAX;
    float* As3 = attn + 16 * NMAX;
    float* Ad3 = attn + 17 * NMAX;

    const int GSMEM = 2 * STAGESZ;   // 40960
    static int s_init = 0;
    static cudaStream_t s1;
    static cudaEvent_t e_fork, e_join;
    if (!s_init) {
        cudaFuncSetAttribute(k_gemm_mma, cudaFuncAttributeMaxDynamicSharedMemorySize, GSMEM);
        cudaStreamCreateWithFlags(&s1, cudaStreamNonBlocking);
        cudaEventCreateWithFlags(&e_fork, cudaEventDisableTiming);
        cudaEventCreateWithFlags(&e_join, cudaEventDisableTiming);
        s_init = 1;
    }

    int nb = (N + 1023) / 1024;
    int rowT = (N + 127) / 128;

    // ---- fork: CSR branch + W2/W3 converts on s1, concurrent with main chain ----
    cudaEventRecord(e_fork, 0);
    cudaStreamWaitEvent(s1, e_fork, 0);
    cudaMemsetAsync(degp, 0, N * sizeof(int), s1);
    k_count<<<(E + 255) / 256, 256, 0, s1>>>(dstp, E);
    k_scan1<<<nb, 1024, 0, s1>>>(N);
    k_scan2<<<1, 64, 0, s1>>>(nb);
    k_scan3<<<(N + 255) / 256, 256, 0, s1>>>(N);
    k_fill_self<<<(N + 255) / 256, 256, 0, s1>>>(N);
    k_fill_edges<<<(E + 255) / 256, 256, 0, s1>>>(srcp, dstp, E);
    k_wconv<<<(512 * 512 + 255) / 256, 256, 0, s1>>>(W2, 512, 512, W2b);
    k_wconv<<<(512 * 128 + 255) / 256, 256, 0, s1>>>(W3, 512, 128, W3b);
    cudaEventRecord(e_join, s1);

    // ---- main chain: layer-1 GEMM prerequisites + GEMM ----
    cudaMemsetAsync(attn, 0, 18 * NMAX * sizeof(float));
    k_aconv<<<(N * 64 + 255) / 256, 256>>>(x, N * 64);
    k_wconv<<<(64 * 512 + 255) / 256, 256>>>(W1, 64, 512, W1b);
    k_gemm_mma<<<dim3(4, rowT), 256, GSMEM>>>(Ab, W1b, Hb, a_src1, a_dst1, As1, Ad1, N, 64, 512, 4);

    // ---- join: need CSR + W2/W3 converts from here on ----
    cudaStreamWaitEvent(0, e_join, 0);

    k_softmax<4><<<(N + 7) / 8, 256>>>(As1, Ad1, N);
    k_aggregate<4, 128><<<N, 128>>>(Hb, b1, N);

    // Layer 2: K=512, M=512
    k_gemm_mma<<<dim3(4, rowT), 256, GSMEM>>>(Ab, W2b, Hb, a_src2, a_dst2, As2, Ad2, N, 512, 512, 4);
    k_softmax<4><<<(N + 7) / 8, 256>>>(As2, Ad2, N);
    k_aggregate<4, 128><<<N, 128>>>(Hb, b2, N);

    // Layer 3: K=512, M=128 (heads=1)
    k_gemm_mma<<<dim3(1, rowT), 256, GSMEM>>>(Ab, W3b, Hb, a_src3, a_dst3, As3, Ad3, N, 512, 128, 1);
    k_softmax<1><<<(N + 7) / 8, 256>>>(As3, Ad3, N);
    k_aggregate<1, 32><<<N, 32>>>(Hb, b3, N);

    // MLP head
    k_fc<<<(N + FC_NB - 1) / FC_NB, 64>>>(fc1w, fc1b, fc2w, fc2b, out, N);
}